// round 11
// baseline (speedup 1.0000x reference)
#include <cuda_runtime.h>
#include <cuda_bf16.h>
#include <cuda_fp8.h>
#include <stdint.h>
#include <math.h>

#define DD 512
#define CC 4096
#define SS 50000

#define BM 128
#define NPANELS ((SS + BM - 1) / BM)   // 391
#define NWORK   (NPANELS * 2)          // 782 items: (panel, codebook half)
#define NCH_I   64                     // 16 tiles x 4 chunks per item
#define NGRID   296                    // 2 CTAs/SM x 148 SMs, persistent

#define ASTRIDE_B 528                  // bytes per A row (132 words % 32 = 4 -> LDSM conflict-free)
#define A_BYTES (BM*ASTRIDE_B)         // 67584
#define BSTRIDE_B 144                  // bytes per B row (36 words % 32 = 4 -> conflict-free)
#define CHUNK_BYTES (128*BSTRIDE_B)    // 18432: 128 codes x 128 K fp8
#define TICK_OFF (A_BYTES + 2*CHUNK_BYTES)     // 104448
#define SMEM_NEED (TICK_OFF + 16)              // 104464 -> still 2 CTAs/SM

// ---------------- scratch ----------------
__device__ __align__(16) uint8_t g_cb8[CC * DD];     // codebook, e4m3
__device__ unsigned long long g_top[SS];             // (orderable fp32 << 32) | ~idx
__device__ int   g_ticket;
__device__ int   g_count[CC];
__device__ float g_proto_sum[DD];
__device__ float g_pcode_sum[DD];
__device__ float g_proto[DD];
__device__ float g_pcode[DD];

// ---------------- helpers ----------------
__device__ __forceinline__ uint32_t smem_u32(const void* p) {
    uint32_t a;
    asm("{ .reg .u64 t; cvta.to.shared.u64 t, %1; cvt.u32.u64 %0, t; }" : "=r"(a) : "l"(p));
    return a;
}
__device__ __forceinline__ void cp16(uint32_t dst, const void* src) {
    asm volatile("cp.async.cg.shared.global [%0], [%1], 16;" :: "r"(dst), "l"(src) : "memory");
}
__device__ __forceinline__ void cp_commit() {
    asm volatile("cp.async.commit_group;" ::: "memory");
}
template <int N>
__device__ __forceinline__ void cp_wait() {
    asm volatile("cp.async.wait_group %0;" :: "n"(N) : "memory");
}
__device__ __forceinline__ void group_bar(int g) {
    asm volatile("bar.sync %0, 128;" :: "r"(4 + g) : "memory");
}
__device__ __forceinline__ void ldsm4(uint32_t r[4], uint32_t addr) {
    asm volatile("ldmatrix.sync.aligned.m8n8.x4.shared.b16 {%0,%1,%2,%3}, [%4];"
                 : "=r"(r[0]), "=r"(r[1]), "=r"(r[2]), "=r"(r[3]) : "r"(addr));
}
// fp8 e4m3 MMA: D(16x8,f32) += A(16x32,e4m3) * B(8x32,e4m3)^T
__device__ __forceinline__ void mma16832(float c[4], const uint32_t a[4], const uint32_t b[2]) {
    asm volatile(
        "mma.sync.aligned.m16n8k32.row.col.f32.e4m3.e4m3.f32 "
        "{%0,%1,%2,%3}, {%4,%5,%6,%7}, {%8,%9}, {%0,%1,%2,%3};\n"
        : "+f"(c[0]), "+f"(c[1]), "+f"(c[2]), "+f"(c[3])
        : "r"(a[0]), "r"(a[1]), "r"(a[2]), "r"(a[3]), "r"(b[0]), "r"(b[1]));
}
// pack 2 floats into e4m3x2; first asm source -> HIGH byte, so pass (hi=b, lo=a)
__device__ __forceinline__ uint16_t f2_e4m3(float a, float b) {
    uint16_t r;
    asm("cvt.rn.satfinite.e4m3x2.f32 %0, %1, %2;" : "=h"(r) : "f"(b), "f"(a));
    return r;
}
__device__ __forceinline__ uint32_t f4_e4m3(float4 v) {
    uint16_t lo = f2_e4m3(v.x, v.y);
    uint16_t hi = f2_e4m3(v.z, v.w);
    return (uint32_t)lo | ((uint32_t)hi << 16);
}
__device__ __forceinline__ uint32_t fkey(float f) {
    uint32_t b = __float_as_uint(f);
    return b ^ ((uint32_t)((int)b >> 31) | 0x80000000u);
}

// ---------------- K1: codebook fp32->e4m3 + init scratch ----------------
__global__ void k_convert(const float* __restrict__ cb) {
    long i = (long)blockIdx.x * blockDim.x + threadIdx.x;
    long stride = (long)gridDim.x * blockDim.x;
    if (i == 0) g_ticket = 0;
    if (i < CC) g_count[i] = 0;
    if (i < DD) { g_proto_sum[i] = 0.f; g_pcode_sum[i] = 0.f; }
    for (long p = i; p < SS; p += stride) g_top[p] = 0ull;
    const long npcb = (long)CC * DD / 4;          // float4 -> 4 bytes
    const float4* cb4 = (const float4*)cb;
    uint32_t* C4 = (uint32_t*)g_cb8;
    for (long p = i; p < npcb; p += stride) C4[p] = f4_e4m3(cb4[p]);
}

// ---------------- K3: persistent fp8 GEMM, work-stolen (panel, half) items ----------------
__global__ void __launch_bounds__(256, 2) k_gemm_argmax(const float* __restrict__ X) {
    extern __shared__ char smem[];
    char* As = smem;
    const uint32_t as_u32 = smem_u32(As);
    const uint32_t bs_u32 = as_u32 + A_BYTES;
    int* s_tick = (int*)(smem + TICK_OFF);

    const int tid = threadIdx.x;
    const int wid = tid >> 5, lane = tid & 31;
    const int warp_n = wid & 1;                        // group id g
    const int warp_m = wid >> 1;                       // 0..3
    const int gid = lane >> 2, tig = lane & 3;

    // ldmatrix lane addresses (proven)
    const uint32_t a_lane = as_u32 + (uint32_t)(warp_m * 32 + (lane & 15)) * ASTRIDE_B
                                   + (uint32_t)(lane >> 4) * 16u;
    const uint32_t b_lane = bs_u32 + (uint32_t)(warp_n * 64 + (lane & 7) + (lane >> 4) * 8) * BSTRIDE_B
                                   + (uint32_t)((lane >> 3) & 1) * 16u;

    // group-local cp slots: group g loads rows [g*64, g*64+64)
    const int gt = warp_m * 32 + lane;                 // 0..127 within group

    const float4* X4 = (const float4*)X;

    while (true) {
        if (tid == 0) s_tick[0] = atomicAdd(&g_ticket, 1);
        __syncthreads();                 // s_tick visible; prev item's A reads complete
        const int w = s_tick[0];
        __syncthreads();
        if (w >= NWORK) break;

        const int panel = w >> 1, nhalf = w & 1;
        const int m0 = panel * BM;
        const uint8_t* cb_half = g_cb8 + (size_t)nhalf * 2048 * DD;
        const int n_base = nhalf * 2048;

        // ---- prologue: issue chunk 0 (tile 0 of this half, K[0:128)) into buffer 0 ----
        {
            const uint8_t* gb = cb_half + (size_t)warp_n * 64 * DD;
            #pragma unroll
            for (int j = 0; j < 4; j++) {
                int s = gt + j * 128;
                int r = s >> 3, v = s & 7;
                cp16(bs_u32 + (uint32_t)(warp_n * 64 + r) * BSTRIDE_B + v * 16,
                     gb + (size_t)r * DD + v * 16);
            }
            cp_commit();
        }

        // ---- A panel: fp32 -> e4m3, proto partial sums (half 0 only) ----
        float ps0 = 0.f, ps1 = 0.f, ps2 = 0.f, ps3 = 0.f;
        #pragma unroll 8
        for (int j = 0; j < 64; j++) {
            int i = tid + j * 256;
            int r = i >> 7, q = i & 127;
            int gr = m0 + r;
            float4 v = make_float4(0.f, 0.f, 0.f, 0.f);
            if (gr < SS) v = X4[(size_t)gr * 128 + q];
            ps0 += v.x; ps1 += v.y; ps2 += v.z; ps3 += v.w;
            *(uint32_t*)(As + r * ASTRIDE_B + q * 4) = f4_e4m3(v);
        }
        __syncthreads();       // A panel visible; groups free-run after this
        if (nhalf == 0) {
            int q4 = (tid & 127) * 4;
            atomicAdd(&g_proto_sum[q4 + 0], ps0);
            atomicAdd(&g_proto_sum[q4 + 1], ps1);
            atomicAdd(&g_proto_sum[q4 + 2], ps2);
            atomicAdd(&g_proto_sum[q4 + 3], ps3);
        }

        float rb_val[2][2];
        int   rb_idx[2][2];
        float acc[2][8][4];

        for (int c = 0; c < NCH_I; c++) {
            const int t  = c >> 2;              // tile within half (0..15)
            const int kc = c & 3;               // 128-K chunk within tile
            const uint32_t buf = bs_u32 + (uint32_t)(c & 1) * CHUNK_BYTES;

            if (kc == 0) {
                #pragma unroll
                for (int mf = 0; mf < 2; mf++)
                    #pragma unroll
                    for (int nf = 0; nf < 8; nf++)
                        #pragma unroll
                        for (int q = 0; q < 4; q++) acc[mf][nf][q] = 0.f;
            }

            cp_wait<0>();          // this thread's loads for chunk c done
            group_bar(warp_n);     // group's rows for chunk c visible; frees other buffer rows

            // ---- issue chunk c+1 (group's own rows) ----
            if (c + 1 < NCH_I) {
                const int c1 = c + 1;
                const uint8_t* gb = cb_half + (size_t)(c1 >> 2) * 128 * DD
                                  + (size_t)warp_n * 64 * DD + (c1 & 3) * 128;
                const uint32_t dst1 = bs_u32 + (uint32_t)(c1 & 1) * CHUNK_BYTES;
                #pragma unroll
                for (int j = 0; j < 4; j++) {
                    int s = gt + j * 128;
                    int r = s >> 3, v = s & 7;
                    cp16(dst1 + (uint32_t)(warp_n * 64 + r) * BSTRIDE_B + v * 16,
                         gb + (size_t)r * DD + v * 16);
                }
            }
            cp_commit();

            // ---- compute 128 K (4 k-steps of 32), per-warp staggered ----
            #pragma unroll
            for (int ks = 0; ks < 4; ks++) {
                const int kss = (ks + warp_m) & 3;
                const uint32_t a_off = (uint32_t)(kc * 128 + kss * 32);
                uint32_t a[2][4];
                ldsm4(a[0], a_lane + a_off);
                ldsm4(a[1], a_lane + 16u * ASTRIDE_B + a_off);
                const uint32_t b_base = b_lane - bs_u32 + buf + kss * 32;
                #pragma unroll
                for (int pair = 0; pair < 4; pair++) {
                    uint32_t b[4];
                    ldsm4(b, b_base + pair * (16u * BSTRIDE_B));
                    mma16832(acc[0][2 * pair],     a[0], b);
                    mma16832(acc[1][2 * pair],     a[1], b);
                    mma16832(acc[0][2 * pair + 1], a[0], b + 2);
                    mma16832(acc[1][2 * pair + 1], a[1], b + 2);
                }
            }

            // ---- end of tile: fused argmax ----
            if (kc == 3) {
                #pragma unroll
                for (int mf = 0; mf < 2; mf++) {
                    #pragma unroll
                    for (int h = 0; h < 2; h++) {
                        float bv = -3.4e38f; int bi = 0;
                        #pragma unroll
                        for (int nf = 0; nf < 8; nf++) {
                            int n = n_base + t * 128 + warp_n * 64 + nf * 8 + tig * 2;
                            float v0 = acc[mf][nf][h * 2 + 0];
                            float v1 = acc[mf][nf][h * 2 + 1];
                            if (v0 > bv || (v0 == bv && n     < bi)) { bv = v0; bi = n; }
                            if (v1 > bv || (v1 == bv && n + 1 < bi)) { bv = v1; bi = n + 1; }
                        }
                        #pragma unroll
                        for (int m = 1; m <= 2; m <<= 1) {
                            float ov = __shfl_xor_sync(0xffffffffu, bv, m);
                            int   oi = __shfl_xor_sync(0xffffffffu, bi, m);
                            if (ov > bv || (ov == bv && oi < bi)) { bv = ov; bi = oi; }
                        }
                        if (t == 0 ||
                            bv > rb_val[mf][h] || (bv == rb_val[mf][h] && bi < rb_idx[mf][h])) {
                            rb_val[mf][h] = bv; rb_idx[mf][h] = bi;
                        }
                    }
                }
            }
        }

        // ---- per-item merge via global atomicMax (monotone key; tie -> smaller idx) ----
        if (tig == 0) {
            #pragma unroll
            for (int mf = 0; mf < 2; mf++)
                #pragma unroll
                for (int h = 0; h < 2; h++) {
                    int gr = m0 + warp_m * 32 + mf * 16 + h * 8 + gid;
                    if (gr < SS) {
                        unsigned long long key =
                            ((unsigned long long)fkey(rb_val[mf][h]) << 32) |
                            (uint32_t)(~rb_idx[mf][h]);
                        atomicMax(&g_top[gr], key);
                    }
                }
        }
    }
}

// ---------------- K4: histogram ----------------
__global__ void k_hist() {
    __shared__ int h[CC];
    for (int i = threadIdx.x; i < CC; i += blockDim.x) h[i] = 0;
    __syncthreads();
    for (int i = blockIdx.x * blockDim.x + threadIdx.x; i < SS; i += gridDim.x * blockDim.x) {
        int idx = (int)(~(uint32_t)g_top[i]);
        atomicAdd(&h[idx], 1);
    }
    __syncthreads();
    for (int i = threadIdx.x; i < CC; i += blockDim.x)
        if (h[i]) atomicAdd(&g_count[i], h[i]);
}

// ---------------- K5: count-weighted codebook sum (exact fp32) ----------------
#define PC_CHUNK 16
__global__ void k_pcode(const float* __restrict__ cb) {
    int d = threadIdx.x;
    int c0 = blockIdx.x * PC_CHUNK;
    float acc = 0.f;
    #pragma unroll
    for (int c = c0; c < c0 + PC_CHUNK; c++) {
        int cnt = g_count[c];
        if (cnt) acc += (float)cnt * cb[(size_t)c * DD + d];
    }
    atomicAdd(&g_pcode_sum[d], acc);
}

// ---------------- K6: finalize ----------------
__global__ void k_finalize() {
    int d = threadIdx.x;
    if (d < DD) {
        const float inv = 1.0f / (float)SS;
        g_proto[d] = g_proto_sum[d] * inv;
        g_pcode[d] = g_pcode_sum[d] * inv;
    }
}

// ---------------- K7: query distances ----------------
__global__ void k_query(const float* __restrict__ X, float* __restrict__ out, int nq) {
    __shared__ float sp[DD], sc[DD];
    for (int i = threadIdx.x; i < DD; i += blockDim.x) { sp[i] = g_proto[i]; sc[i] = g_pcode[i]; }
    __syncthreads();
    int wid = threadIdx.x >> 5, lane = threadIdx.x & 31;
    int q = blockIdx.x * (blockDim.x >> 5) + wid;
    if (q >= nq) return;
    const float4* row = (const float4*)&X[(size_t)(SS + q) * DD];
    float s1 = 0.f, s2 = 0.f;
    #pragma unroll
    for (int j = 0; j < 4; j++) {
        int idx = lane + j * 32;
        float4 v = row[idx];
        int b = idx * 4;
        float d;
        d = v.x - sp[b + 0]; s1 += d * d;  d = v.x - sc[b + 0]; s2 += d * d;
        d = v.y - sp[b + 1]; s1 += d * d;  d = v.y - sc[b + 1]; s2 += d * d;
        d = v.z - sp[b + 2]; s1 += d * d;  d = v.z - sc[b + 2]; s2 += d * d;
        d = v.w - sp[b + 3]; s1 += d * d;  d = v.w - sc[b + 3]; s2 += d * d;
    }
    #pragma unroll
    for (int m = 16; m > 0; m >>= 1) {
        s1 += __shfl_xor_sync(0xffffffffu, s1, m);
        s2 += __shfl_xor_sync(0xffffffffu, s2, m);
    }
    if (lane == 0) out[q] = 0.5f * (sqrtf(s1) + sqrtf(s2));
}

// ---------------- launch ----------------
extern "C" void kernel_launch(void* const* d_in, const int* in_sizes, int n_in,
                              void* d_out, int out_size) {
    const float* X  = (const float*)d_in[0];
    const float* cb = (const float*)d_in[1];
    int N  = in_sizes[0] / DD;
    int nq = N - SS;
    float* out = (float*)d_out;

    cudaFuncSetAttribute(k_gemm_argmax, cudaFuncAttributeMaxDynamicSharedMemorySize, SMEM_NEED);

    k_convert<<<512, 256>>>(cb);
    k_gemm_argmax<<<NGRID, 256, SMEM_NEED>>>(X);
    k_hist<<<64, 256>>>();
    k_pcode<<<CC / PC_CHUNK, DD>>>(cb);
    k_finalize<<<1, DD>>>();
    k_query<<<(nq + 7) / 8, 256>>>(X, out, nq);
}

// round 12
// speedup vs baseline: 1.0708x; 1.0708x over previous
#include <cuda_runtime.h>
#include <cuda_bf16.h>
#include <cuda_fp8.h>
#include <stdint.h>
#include <math.h>

#define DD 512
#define CC 4096
#define SS 50000

#define BM 128
#define NPANELS ((SS + BM - 1) / BM)   // 391
#define NWORK   (NPANELS * 4)          // 1564 items: (panel, codebook quarter)
#define NCH_I   32                     // 8 tiles x 4 chunks per item
#define NGRID   296                    // 2 CTAs/SM x 148 SMs, persistent

#define ASTRIDE_B 528                  // bytes per A row (132 words % 32 = 4 -> LDSM conflict-free)
#define A_BYTES (BM*ASTRIDE_B)         // 67584
#define BSTRIDE_B 144                  // bytes per B row (36 words % 32 = 4 -> conflict-free)
#define CHUNK_BYTES (128*BSTRIDE_B)    // 18432: 128 codes x 128 K fp8
#define TICK_OFF (A_BYTES + 2*CHUNK_BYTES)     // 104448
#define SMEM_NEED (TICK_OFF + 16)              // 104464 -> 2 CTAs/SM

// ---------------- scratch ----------------
__device__ __align__(16) uint8_t g_sup8[NPANELS * BM * DD];  // support e4m3, zero-padded
__device__ __align__(16) uint8_t g_cb8[CC * DD];             // codebook e4m3
__device__ unsigned long long g_top[SS];   // (orderable fp32 << 32) | ~idx
__device__ int   g_ticket;
__device__ int   g_count[CC];
__device__ float g_proto_sum[DD];
__device__ float g_pcode_sum[DD];
__device__ float g_proto[DD];
__device__ float g_pcode[DD];

// ---------------- helpers ----------------
__device__ __forceinline__ uint32_t smem_u32(const void* p) {
    uint32_t a;
    asm("{ .reg .u64 t; cvta.to.shared.u64 t, %1; cvt.u32.u64 %0, t; }" : "=r"(a) : "l"(p));
    return a;
}
__device__ __forceinline__ void cp16(uint32_t dst, const void* src) {
    asm volatile("cp.async.cg.shared.global [%0], [%1], 16;" :: "r"(dst), "l"(src) : "memory");
}
__device__ __forceinline__ void cp_commit() {
    asm volatile("cp.async.commit_group;" ::: "memory");
}
template <int N>
__device__ __forceinline__ void cp_wait() {
    asm volatile("cp.async.wait_group %0;" :: "n"(N) : "memory");
}
__device__ __forceinline__ void group_bar(int g) {
    asm volatile("bar.sync %0, 128;" :: "r"(4 + g) : "memory");
}
__device__ __forceinline__ void ldsm4(uint32_t r[4], uint32_t addr) {
    asm volatile("ldmatrix.sync.aligned.m8n8.x4.shared.b16 {%0,%1,%2,%3}, [%4];"
                 : "=r"(r[0]), "=r"(r[1]), "=r"(r[2]), "=r"(r[3]) : "r"(addr));
}
// fp8 e4m3 MMA: D(16x8,f32) += A(16x32,e4m3) * B(8x32,e4m3)^T
__device__ __forceinline__ void mma16832(float c[4], const uint32_t a[4], const uint32_t b[2]) {
    asm volatile(
        "mma.sync.aligned.m16n8k32.row.col.f32.e4m3.e4m3.f32 "
        "{%0,%1,%2,%3}, {%4,%5,%6,%7}, {%8,%9}, {%0,%1,%2,%3};\n"
        : "+f"(c[0]), "+f"(c[1]), "+f"(c[2]), "+f"(c[3])
        : "r"(a[0]), "r"(a[1]), "r"(a[2]), "r"(a[3]), "r"(b[0]), "r"(b[1]));
}
// pack 2 floats into e4m3x2; first asm source -> HIGH byte, so pass (hi=b, lo=a)
__device__ __forceinline__ uint16_t f2_e4m3(float a, float b) {
    uint16_t r;
    asm("cvt.rn.satfinite.e4m3x2.f32 %0, %1, %2;" : "=h"(r) : "f"(b), "f"(a));
    return r;
}
__device__ __forceinline__ uint32_t f4_e4m3(float4 v) {
    uint16_t lo = f2_e4m3(v.x, v.y);
    uint16_t hi = f2_e4m3(v.z, v.w);
    return (uint32_t)lo | ((uint32_t)hi << 16);
}
__device__ __forceinline__ uint32_t fkey(float f) {
    uint32_t b = __float_as_uint(f);
    return b ^ ((uint32_t)((int)b >> 31) | 0x80000000u);
}

// ---------------- K1: codebook fp32->e4m3 + init scratch ----------------
__global__ void k_convert(const float* __restrict__ cb) {
    long i = (long)blockIdx.x * blockDim.x + threadIdx.x;
    long stride = (long)gridDim.x * blockDim.x;
    if (i == 0) g_ticket = 0;
    if (i < CC) g_count[i] = 0;
    if (i < DD) { g_proto_sum[i] = 0.f; g_pcode_sum[i] = 0.f; }
    for (long p = i; p < SS; p += stride) g_top[p] = 0ull;
    const long npcb = (long)CC * DD / 4;
    const float4* cb4 = (const float4*)cb;
    uint32_t* C4 = (uint32_t*)g_cb8;
    for (long p = i; p < npcb; p += stride) C4[p] = f4_e4m3(cb4[p]);
}

// ---------------- K2: support fp32->e4m3 (zero-padded) + proto column sums ----------------
__global__ void __launch_bounds__(256) k_supconv(const float* __restrict__ X) {
    const int tid = threadIdx.x;
    const int m0 = blockIdx.x * BM;
    const int q  = tid & 127;        // float4 piece within row
    const int rh = tid >> 7;         // row half (0/1)
    const float4* X4 = (const float4*)X;
    uint32_t* S4 = (uint32_t*)g_sup8;
    float s0 = 0.f, s1 = 0.f, s2 = 0.f, s3 = 0.f;
    #pragma unroll 4
    for (int j = 0; j < 64; j++) {
        int r = rh * 64 + j;
        int gr = m0 + r;
        float4 v = make_float4(0.f, 0.f, 0.f, 0.f);
        if (gr < SS) v = X4[(size_t)gr * 128 + q];
        s0 += v.x; s1 += v.y; s2 += v.z; s3 += v.w;
        S4[(size_t)(m0 + r) * 128 + q] = f4_e4m3(v);
    }
    int q4 = q * 4;
    atomicAdd(&g_proto_sum[q4 + 0], s0);
    atomicAdd(&g_proto_sum[q4 + 1], s1);
    atomicAdd(&g_proto_sum[q4 + 2], s2);
    atomicAdd(&g_proto_sum[q4 + 3], s3);
}

// ---------------- K3: persistent fp8 GEMM, work-stolen (panel, quarter) items ----------------
__global__ void __launch_bounds__(256, 2) k_gemm_argmax() {
    extern __shared__ char smem[];
    const uint32_t as_u32 = smem_u32(smem);
    const uint32_t bs_u32 = as_u32 + A_BYTES;
    int* s_tick = (int*)(smem + TICK_OFF);

    const int tid = threadIdx.x;
    const int wid = tid >> 5, lane = tid & 31;
    const int warp_n = wid & 1;                        // group id g
    const int warp_m = wid >> 1;                       // 0..3
    const int gid = lane >> 2, tig = lane & 3;

    // ldmatrix lane addresses (proven)
    const uint32_t a_lane = as_u32 + (uint32_t)(warp_m * 32 + (lane & 15)) * ASTRIDE_B
                                   + (uint32_t)(lane >> 4) * 16u;
    const uint32_t b_lane = bs_u32 + (uint32_t)(warp_n * 64 + (lane & 7) + (lane >> 4) * 8) * BSTRIDE_B
                                   + (uint32_t)((lane >> 3) & 1) * 16u;

    // B cp slots: group g loads rows [g*64, g*64+64), 4 x 16B per thread per chunk
    const int gt = warp_m * 32 + lane;                 // 0..127 within group

    while (true) {
        if (tid == 0) s_tick[0] = atomicAdd(&g_ticket, 1);
        __syncthreads();                 // joins groups; prev item's smem reads complete
        const int w = s_tick[0];
        __syncthreads();
        if (w >= NWORK) break;

        const int panel = w >> 2, quarter = w & 3;
        const int m0 = panel * BM;
        const uint8_t* cb_q = g_cb8 + (size_t)quarter * 1024 * DD;
        const int n_base = quarter * 1024;

        // ---- issue A panel (fp8, 64KB, L2-resident) + B chunk 0; one group ----
        {
            const uint8_t* ga = g_sup8 + (size_t)m0 * DD;
            #pragma unroll
            for (int j = 0; j < 16; j++) {
                int s = tid + j * 256;               // 0..4095
                int r = s >> 5, v = s & 31;
                cp16(as_u32 + (uint32_t)r * ASTRIDE_B + v * 16,
                     ga + (size_t)r * DD + v * 16);
            }
            const uint8_t* gb = cb_q + (size_t)warp_n * 64 * DD;
            #pragma unroll
            for (int j = 0; j < 4; j++) {
                int s = gt + j * 128;
                int r = s >> 3, v = s & 7;
                cp16(bs_u32 + (uint32_t)(warp_n * 64 + r) * BSTRIDE_B + v * 16,
                     gb + (size_t)r * DD + v * 16);
            }
            cp_commit();
        }

        float rb_val[2][2];
        int   rb_idx[2][2];
        float acc[2][8][4];

        for (int c = 0; c < NCH_I; c++) {
            const int t  = c >> 2;              // tile within quarter (0..7)
            const int kc = c & 3;               // 128-K chunk within tile
            const uint32_t buf = bs_u32 + (uint32_t)(c & 1) * CHUNK_BYTES;

            if (kc == 0) {
                #pragma unroll
                for (int mf = 0; mf < 2; mf++)
                    #pragma unroll
                    for (int nf = 0; nf < 8; nf++)
                        #pragma unroll
                        for (int q = 0; q < 4; q++) acc[mf][nf][q] = 0.f;
            }

            cp_wait<0>();
            if (c == 0) __syncthreads();        // A panel (loaded by all threads) visible
            else        group_bar(warp_n);      // group's chunk rows visible; frees other buffer

            // ---- issue chunk c+1 (group's own rows) ----
            if (c + 1 < NCH_I) {
                const int c1 = c + 1;
                const uint8_t* gb = cb_q + (size_t)(c1 >> 2) * 128 * DD
                                  + (size_t)warp_n * 64 * DD + (c1 & 3) * 128;
                const uint32_t dst1 = bs_u32 + (uint32_t)(c1 & 1) * CHUNK_BYTES;
                #pragma unroll
                for (int j = 0; j < 4; j++) {
                    int s = gt + j * 128;
                    int r = s >> 3, v = s & 7;
                    cp16(dst1 + (uint32_t)(warp_n * 64 + r) * BSTRIDE_B + v * 16,
                         gb + (size_t)r * DD + v * 16);
                }
            }
            cp_commit();

            // ---- compute 128 K (4 k-steps of 32), per-warp staggered ----
            #pragma unroll
            for (int ks = 0; ks < 4; ks++) {
                const int kss = (ks + warp_m) & 3;
                const uint32_t a_off = (uint32_t)(kc * 128 + kss * 32);
                uint32_t a[2][4];
                ldsm4(a[0], a_lane + a_off);
                ldsm4(a[1], a_lane + 16u * ASTRIDE_B + a_off);
                const uint32_t b_base = b_lane - bs_u32 + buf + kss * 32;
                #pragma unroll
                for (int pair = 0; pair < 4; pair++) {
                    uint32_t b[4];
                    ldsm4(b, b_base + pair * (16u * BSTRIDE_B));
                    mma16832(acc[0][2 * pair],     a[0], b);
                    mma16832(acc[1][2 * pair],     a[1], b);
                    mma16832(acc[0][2 * pair + 1], a[0], b + 2);
                    mma16832(acc[1][2 * pair + 1], a[1], b + 2);
                }
            }

            // ---- end of tile: fused argmax ----
            if (kc == 3) {
                #pragma unroll
                for (int mf = 0; mf < 2; mf++) {
                    #pragma unroll
                    for (int h = 0; h < 2; h++) {
                        float bv = -3.4e38f; int bi = 0;
                        #pragma unroll
                        for (int nf = 0; nf < 8; nf++) {
                            int n = n_base + t * 128 + warp_n * 64 + nf * 8 + tig * 2;
                            float v0 = acc[mf][nf][h * 2 + 0];
                            float v1 = acc[mf][nf][h * 2 + 1];
                            if (v0 > bv || (v0 == bv && n     < bi)) { bv = v0; bi = n; }
                            if (v1 > bv || (v1 == bv && n + 1 < bi)) { bv = v1; bi = n + 1; }
                        }
                        #pragma unroll
                        for (int m = 1; m <= 2; m <<= 1) {
                            float ov = __shfl_xor_sync(0xffffffffu, bv, m);
                            int   oi = __shfl_xor_sync(0xffffffffu, bi, m);
                            if (ov > bv || (ov == bv && oi < bi)) { bv = ov; bi = oi; }
                        }
                        if (t == 0 ||
                            bv > rb_val[mf][h] || (bv == rb_val[mf][h] && bi < rb_idx[mf][h])) {
                            rb_val[mf][h] = bv; rb_idx[mf][h] = bi;
                        }
                    }
                }
            }
        }

        // ---- per-item merge via global atomicMax (monotone key; tie -> smaller idx) ----
        if (tig == 0) {
            #pragma unroll
            for (int mf = 0; mf < 2; mf++)
                #pragma unroll
                for (int h = 0; h < 2; h++) {
                    int gr = m0 + warp_m * 32 + mf * 16 + h * 8 + gid;
                    if (gr < SS) {
                        unsigned long long key =
                            ((unsigned long long)fkey(rb_val[mf][h]) << 32) |
                            (uint32_t)(~rb_idx[mf][h]);
                        atomicMax(&g_top[gr], key);
                    }
                }
        }
    }
}

// ---------------- K4: histogram ----------------
__global__ void k_hist() {
    __shared__ int h[CC];
    for (int i = threadIdx.x; i < CC; i += blockDim.x) h[i] = 0;
    __syncthreads();
    for (int i = blockIdx.x * blockDim.x + threadIdx.x; i < SS; i += gridDim.x * blockDim.x) {
        int idx = (int)(~(uint32_t)g_top[i]);
        atomicAdd(&h[idx], 1);
    }
    __syncthreads();
    for (int i = threadIdx.x; i < CC; i += blockDim.x)
        if (h[i]) atomicAdd(&g_count[i], h[i]);
}

// ---------------- K5: count-weighted codebook sum (exact fp32) ----------------
#define PC_CHUNK 16
__global__ void k_pcode(const float* __restrict__ cb) {
    int d = threadIdx.x;
    int c0 = blockIdx.x * PC_CHUNK;
    float acc = 0.f;
    #pragma unroll
    for (int c = c0; c < c0 + PC_CHUNK; c++) {
        int cnt = g_count[c];
        if (cnt) acc += (float)cnt * cb[(size_t)c * DD + d];
    }
    atomicAdd(&g_pcode_sum[d], acc);
}

// ---------------- K6: finalize ----------------
__global__ void k_finalize() {
    int d = threadIdx.x;
    if (d < DD) {
        const float inv = 1.0f / (float)SS;
        g_proto[d] = g_proto_sum[d] * inv;
        g_pcode[d] = g_pcode_sum[d] * inv;
    }
}

// ---------------- K7: query distances ----------------
__global__ void k_query(const float* __restrict__ X, float* __restrict__ out, int nq) {
    __shared__ float sp[DD], sc[DD];
    for (int i = threadIdx.x; i < DD; i += blockDim.x) { sp[i] = g_proto[i]; sc[i] = g_pcode[i]; }
    __syncthreads();
    int wid = threadIdx.x >> 5, lane = threadIdx.x & 31;
    int q = blockIdx.x * (blockDim.x >> 5) + wid;
    if (q >= nq) return;
    const float4* row = (const float4*)&X[(size_t)(SS + q) * DD];
    float s1 = 0.f, s2 = 0.f;
    #pragma unroll
    for (int j = 0; j < 4; j++) {
        int idx = lane + j * 32;
        float4 v = row[idx];
        int b = idx * 4;
        float d;
        d = v.x - sp[b + 0]; s1 += d * d;  d = v.x - sc[b + 0]; s2 += d * d;
        d = v.y - sp[b + 1]; s1 += d * d;  d = v.y - sc[b + 1]; s2 += d * d;
        d = v.z - sp[b + 2]; s1 += d * d;  d = v.z - sc[b + 2]; s2 += d * d;
        d = v.w - sp[b + 3]; s1 += d * d;  d = v.w - sc[b + 3]; s2 += d * d;
    }
    #pragma unroll
    for (int m = 16; m > 0; m >>= 1) {
        s1 += __shfl_xor_sync(0xffffffffu, s1, m);
        s2 += __shfl_xor_sync(0xffffffffu, s2, m);
    }
    if (lane == 0) out[q] = 0.5f * (sqrtf(s1) + sqrtf(s2));
}

// ---------------- launch ----------------
extern "C" void kernel_launch(void* const* d_in, const int* in_sizes, int n_in,
                              void* d_out, int out_size) {
    const float* X  = (const float*)d_in[0];
    const float* cb = (const float*)d_in[1];
    int N  = in_sizes[0] / DD;
    int nq = N - SS;
    float* out = (float*)d_out;

    cudaFuncSetAttribute(k_gemm_argmax, cudaFuncAttributeMaxDynamicSharedMemorySize, SMEM_NEED);

    k_convert<<<512, 256>>>(cb);
    k_supconv<<<NPANELS, 256>>>(X);
    k_gemm_argmax<<<NGRID, 256, SMEM_NEED>>>();
    k_hist<<<64, 256>>>();
    k_pcode<<<CC / PC_CHUNK, DD>>>(cb);
    k_finalize<<<1, DD>>>();
    k_query<<<(nq + 7) / 8, 256>>>(X, out, nq);
}

// round 13
// speedup vs baseline: 1.2015x; 1.1221x over previous
#include <cuda_runtime.h>
#include <cuda_bf16.h>
#include <cuda_fp8.h>
#include <stdint.h>
#include <math.h>

#define DD 512
#define CC 4096
#define SS 50000

#define BM 128
#define NPANELS ((SS + BM - 1) / BM)   // 391
#define NCHUNKS 128                    // 32 tiles x 4 chunks (128 K fp8 each)

#define ASTRIDE_B 528                  // bytes per A row (132 words % 32 = 4 -> LDSM conflict-free)
#define A_BYTES (BM*ASTRIDE_B)         // 67584
#define BSTRIDE_B 144                  // bytes per B row (36 words % 32 = 4 -> conflict-free)
#define CHUNK_BYTES (128*BSTRIDE_B)    // 18432: 128 codes x 128 K fp8
#define SMEM_NEED (A_BYTES + 2*CHUNK_BYTES)   // 104448 -> 2 CTAs/SM

// ---------------- scratch ----------------
__device__ __align__(16) uint8_t g_cb8[CC * DD];     // codebook, e4m3
__device__ unsigned long long g_top[SS];             // (orderable fp32 << 32) | ~idx
__device__ int   g_count[CC];
__device__ float g_proto_sum[DD];
__device__ float g_pcode_sum[DD];
__device__ float g_proto[DD];
__device__ float g_pcode[DD];

// ---------------- helpers ----------------
__device__ __forceinline__ uint32_t smem_u32(const void* p) {
    uint32_t a;
    asm("{ .reg .u64 t; cvta.to.shared.u64 t, %1; cvt.u32.u64 %0, t; }" : "=r"(a) : "l"(p));
    return a;
}
__device__ __forceinline__ void cp16(uint32_t dst, const void* src) {
    asm volatile("cp.async.cg.shared.global [%0], [%1], 16;" :: "r"(dst), "l"(src) : "memory");
}
__device__ __forceinline__ void cp_commit() {
    asm volatile("cp.async.commit_group;" ::: "memory");
}
template <int N>
__device__ __forceinline__ void cp_wait() {
    asm volatile("cp.async.wait_group %0;" :: "n"(N) : "memory");
}
__device__ __forceinline__ void group_bar(int g) {
    asm volatile("bar.sync %0, 128;" :: "r"(4 + g) : "memory");
}
__device__ __forceinline__ void ldsm4(uint32_t r[4], uint32_t addr) {
    asm volatile("ldmatrix.sync.aligned.m8n8.x4.shared.b16 {%0,%1,%2,%3}, [%4];"
                 : "=r"(r[0]), "=r"(r[1]), "=r"(r[2]), "=r"(r[3]) : "r"(addr));
}
// fp8 e4m3 MMA: D(16x8,f32) += A(16x32,e4m3) * B(8x32,e4m3)^T
__device__ __forceinline__ void mma16832(float c[4], const uint32_t a[4], const uint32_t b[2]) {
    asm volatile(
        "mma.sync.aligned.m16n8k32.row.col.f32.e4m3.e4m3.f32 "
        "{%0,%1,%2,%3}, {%4,%5,%6,%7}, {%8,%9}, {%0,%1,%2,%3};\n"
        : "+f"(c[0]), "+f"(c[1]), "+f"(c[2]), "+f"(c[3])
        : "r"(a[0]), "r"(a[1]), "r"(a[2]), "r"(a[3]), "r"(b[0]), "r"(b[1]));
}
// pack 2 floats into e4m3x2; first asm source -> HIGH byte, so pass (hi=b, lo=a)
__device__ __forceinline__ uint16_t f2_e4m3(float a, float b) {
    uint16_t r;
    asm("cvt.rn.satfinite.e4m3x2.f32 %0, %1, %2;" : "=h"(r) : "f"(b), "f"(a));
    return r;
}
__device__ __forceinline__ uint32_t f4_e4m3(float4 v) {
    uint16_t lo = f2_e4m3(v.x, v.y);
    uint16_t hi = f2_e4m3(v.z, v.w);
    return (uint32_t)lo | ((uint32_t)hi << 16);
}
__device__ __forceinline__ uint32_t fkey(float f) {
    uint32_t b = __float_as_uint(f);
    return b ^ ((uint32_t)((int)b >> 31) | 0x80000000u);
}

// ---------------- K1: codebook fp32->e4m3 + init scratch ----------------
__global__ void k_convert(const float* __restrict__ cb) {
    long i = (long)blockIdx.x * blockDim.x + threadIdx.x;
    long stride = (long)gridDim.x * blockDim.x;
    if (i < CC) g_count[i] = 0;
    if (i < DD) { g_proto_sum[i] = 0.f; g_pcode_sum[i] = 0.f; }
    for (long p = i; p < SS; p += stride) g_top[p] = 0ull;
    const long npcb = (long)CC * DD / 4;          // float4 -> 4 bytes
    const float4* cb4 = (const float4*)cb;
    uint32_t* C4 = (uint32_t*)g_cb8;
    for (long p = i; p < npcb; p += stride) C4[p] = f4_e4m3(cb4[p]);
}

// ---------------- K3: fp8 GEMM, 2 CTAs/SM, split half-pipelines, tree argmax ----------------
__global__ void __launch_bounds__(256, 2) k_gemm_argmax(const float* __restrict__ X) {
    extern __shared__ char smem[];
    char* As = smem;
    const uint32_t as_u32 = smem_u32(As);
    const uint32_t bs_u32 = as_u32 + A_BYTES;

    const int tid = threadIdx.x;
    const int wid = tid >> 5, lane = tid & 31;
    const int warp_n = wid & 1;                        // group id g
    const int warp_m = wid >> 1;                       // 0..3
    const int gid = lane >> 2, tig = lane & 3;
    const int m0 = blockIdx.x * BM;
    const int rot = ((blockIdx.x / 148) & 1) << 4;     // tile rotation for co-resident CTAs

    // ldmatrix lane addresses (proven)
    const uint32_t a_lane = as_u32 + (uint32_t)(warp_m * 32 + (lane & 15)) * ASTRIDE_B
                                   + (uint32_t)(lane >> 4) * 16u;
    const uint32_t b_lane = bs_u32 + (uint32_t)(warp_n * 64 + (lane & 7) + (lane >> 4) * 8) * BSTRIDE_B
                                   + (uint32_t)((lane >> 3) & 1) * 16u;

    // group-local cp slots: group g loads rows [g*64, g*64+64)
    const int gt = warp_m * 32 + lane;                 // 0..127 within group

    // ---- prologue: issue chunk 0 (tile rot, K[0:128)) into buffer 0 ----
    {
        const uint8_t* gb = g_cb8 + (size_t)rot * 128 * DD + (size_t)warp_n * 64 * DD;
        #pragma unroll
        for (int j = 0; j < 4; j++) {
            int s = gt + j * 128;
            int r = s >> 3, v = s & 7;
            cp16(bs_u32 + (uint32_t)(warp_n * 64 + r) * BSTRIDE_B + v * 16,
                 gb + (size_t)r * DD + v * 16);
        }
        cp_commit();
    }

    // ---- A panel: fp32 -> e4m3, accumulate proto partial sums ----
    const float4* X4 = (const float4*)X;
    float ps0 = 0.f, ps1 = 0.f, ps2 = 0.f, ps3 = 0.f;
    #pragma unroll 8
    for (int j = 0; j < 64; j++) {
        int i = tid + j * 256;
        int r = i >> 7, q = i & 127;
        int gr = m0 + r;
        float4 v = make_float4(0.f, 0.f, 0.f, 0.f);
        if (gr < SS) v = X4[(size_t)gr * 128 + q];
        ps0 += v.x; ps1 += v.y; ps2 += v.z; ps3 += v.w;
        *(uint32_t*)(As + r * ASTRIDE_B + q * 4) = f4_e4m3(v);
    }
    __syncthreads();       // A panel visible to all warps; groups free-run after this
    {
        int q4 = (tid & 127) * 4;
        atomicAdd(&g_proto_sum[q4 + 0], ps0);
        atomicAdd(&g_proto_sum[q4 + 1], ps1);
        atomicAdd(&g_proto_sum[q4 + 2], ps2);
        atomicAdd(&g_proto_sum[q4 + 3], ps3);
    }

    float rb_val[2][2];
    int   rb_idx[2][2];
    #pragma unroll
    for (int a2 = 0; a2 < 2; a2++)
        #pragma unroll
        for (int b2 = 0; b2 < 2; b2++) { rb_val[a2][b2] = -3.4e38f; rb_idx[a2][b2] = 0x7FFFFFFF; }

    float acc[2][8][4];

    for (int c = 0; c < NCHUNKS; c++) {
        const int t  = ((c >> 2) + rot) & 31;   // rotated code tile
        const int kc = c & 3;                   // 128-K chunk within tile
        const uint32_t buf = bs_u32 + (uint32_t)(c & 1) * CHUNK_BYTES;

        if (kc == 0) {
            #pragma unroll
            for (int mf = 0; mf < 2; mf++)
                #pragma unroll
                for (int nf = 0; nf < 8; nf++)
                    #pragma unroll
                    for (int q = 0; q < 4; q++) acc[mf][nf][q] = 0.f;
        }

        cp_wait<0>();          // this thread's loads for chunk c done
        group_bar(warp_n);     // whole group's rows for chunk c visible; frees other buffer rows

        // ---- issue chunk c+1 (group's own rows) into the other buffer ----
        if (c + 1 < NCHUNKS) {
            const int c1 = c + 1;
            const int t1 = ((c1 >> 2) + rot) & 31;
            const uint8_t* gb = g_cb8 + (size_t)t1 * 128 * DD + (size_t)warp_n * 64 * DD + (c1 & 3) * 128;
            const uint32_t dst1 = bs_u32 + (uint32_t)((c1 & 1)) * CHUNK_BYTES;
            #pragma unroll
            for (int j = 0; j < 4; j++) {
                int s = gt + j * 128;
                int r = s >> 3, v = s & 7;
                cp16(dst1 + (uint32_t)(warp_n * 64 + r) * BSTRIDE_B + v * 16,
                     gb + (size_t)r * DD + v * 16);
            }
        }
        cp_commit();

        // ---- compute 128 K (4 k-steps of 32), per-warp staggered start ----
        #pragma unroll
        for (int ks = 0; ks < 4; ks++) {
            const int kss = (ks + warp_m) & 3;
            const uint32_t a_off = (uint32_t)(kc * 128 + kss * 32);
            uint32_t a[2][4];
            ldsm4(a[0], a_lane + a_off);
            ldsm4(a[1], a_lane + 16u * ASTRIDE_B + a_off);
            const uint32_t b_base = b_lane - bs_u32 + buf + kss * 32;
            #pragma unroll
            for (int pair = 0; pair < 4; pair++) {
                uint32_t b[4];
                ldsm4(b, b_base + pair * (16u * BSTRIDE_B));
                mma16832(acc[0][2 * pair],     a[0], b);
                mma16832(acc[1][2 * pair],     a[1], b);
                mma16832(acc[0][2 * pair + 1], a[0], b + 2);
                mma16832(acc[1][2 * pair + 1], a[1], b + 2);
            }
        }

        // ---- end of tile: tree argmax (short dependency chains, no per-tile shuffles) ----
        if (kc == 3) {
            #pragma unroll
            for (int mf = 0; mf < 2; mf++) {
                #pragma unroll
                for (int h = 0; h < 2; h++) {
                    float bv[8]; int bidx[8];
                    const int nb = t * 128 + warp_n * 64 + tig * 2;
                    #pragma unroll
                    for (int nf = 0; nf < 8; nf++) {
                        float v0 = acc[mf][nf][h * 2 + 0];
                        float v1 = acc[mf][nf][h * 2 + 1];
                        bool g = v1 > v0;                         // tie keeps lower n
                        bv[nf]   = g ? v1 : v0;
                        bidx[nf] = nb + nf * 8 + (g ? 1 : 0);
                    }
                    #pragma unroll
                    for (int s = 4; s > 0; s >>= 1)
                        #pragma unroll
                        for (int i = 0; i < s; i++) {
                            bool g = bv[i + s] > bv[i];           // tie keeps lower n (i side)
                            bv[i]   = g ? bv[i + s] : bv[i];
                            bidx[i] = g ? bidx[i + s] : bidx[i];
                        }
                    if (bv[0] > rb_val[mf][h] ||
                        (bv[0] == rb_val[mf][h] && bidx[0] < rb_idx[mf][h])) {
                        rb_val[mf][h] = bv[0]; rb_idx[mf][h] = bidx[0];
                    }
                }
            }
        }
    }

    // ---- once: cross-lane (tig) merge, then global atomicMax (monotone key) ----
    #pragma unroll
    for (int mf = 0; mf < 2; mf++)
        #pragma unroll
        for (int h = 0; h < 2; h++) {
            float bv = rb_val[mf][h]; int bi = rb_idx[mf][h];
            #pragma unroll
            for (int m = 1; m <= 2; m <<= 1) {
                float ov = __shfl_xor_sync(0xffffffffu, bv, m);
                int   oi = __shfl_xor_sync(0xffffffffu, bi, m);
                if (ov > bv || (ov == bv && oi < bi)) { bv = ov; bi = oi; }
            }
            if (tig == 0) {
                int gr = m0 + warp_m * 32 + mf * 16 + h * 8 + gid;
                if (gr < SS) {
                    unsigned long long key =
                        ((unsigned long long)fkey(bv) << 32) | (uint32_t)(~bi);
                    atomicMax(&g_top[gr], key);
                }
            }
        }
}

// ---------------- K4: histogram ----------------
__global__ void k_hist() {
    __shared__ int h[CC];
    for (int i = threadIdx.x; i < CC; i += blockDim.x) h[i] = 0;
    __syncthreads();
    for (int i = blockIdx.x * blockDim.x + threadIdx.x; i < SS; i += gridDim.x * blockDim.x) {
        int idx = (int)(~(uint32_t)g_top[i]);
        atomicAdd(&h[idx], 1);
    }
    __syncthreads();
    for (int i = threadIdx.x; i < CC; i += blockDim.x)
        if (h[i]) atomicAdd(&g_count[i], h[i]);
}

// ---------------- K5: count-weighted codebook sum (exact fp32) ----------------
#define PC_CHUNK 16
__global__ void k_pcode(const float* __restrict__ cb) {
    int d = threadIdx.x;
    int c0 = blockIdx.x * PC_CHUNK;
    float acc = 0.f;
    #pragma unroll
    for (int c = c0; c < c0 + PC_CHUNK; c++) {
        int cnt = g_count[c];
        if (cnt) acc += (float)cnt * cb[(size_t)c * DD + d];
    }
    atomicAdd(&g_pcode_sum[d], acc);
}

// ---------------- K6: finalize ----------------
__global__ void k_finalize() {
    int d = threadIdx.x;
    if (d < DD) {
        const float inv = 1.0f / (float)SS;
        g_proto[d] = g_proto_sum[d] * inv;
        g_pcode[d] = g_pcode_sum[d] * inv;
    }
}

// ---------------- K7: query distances ----------------
__global__ void k_query(const float* __restrict__ X, float* __restrict__ out, int nq) {
    __shared__ float sp[DD], sc[DD];
    for (int i = threadIdx.x; i < DD; i += blockDim.x) { sp[i] = g_proto[i]; sc[i] = g_pcode[i]; }
    __syncthreads();
    int wid = threadIdx.x >> 5, lane = threadIdx.x & 31;
    int q = blockIdx.x * (blockDim.x >> 5) + wid;
    if (q >= nq) return;
    const float4* row = (const float4*)&X[(size_t)(SS + q) * DD];
    float s1 = 0.f, s2 = 0.f;
    #pragma unroll
    for (int j = 0; j < 4; j++) {
        int idx = lane + j * 32;
        float4 v = row[idx];
        int b = idx * 4;
        float d;
        d = v.x - sp[b + 0]; s1 += d * d;  d = v.x - sc[b + 0]; s2 += d * d;
        d = v.y - sp[b + 1]; s1 += d * d;  d = v.y - sc[b + 1]; s2 += d * d;
        d = v.z - sp[b + 2]; s1 += d * d;  d = v.z - sc[b + 2]; s2 += d * d;
        d = v.w - sp[b + 3]; s1 += d * d;  d = v.w - sc[b + 3]; s2 += d * d;
    }
    #pragma unroll
    for (int m = 16; m > 0; m >>= 1) {
        s1 += __shfl_xor_sync(0xffffffffu, s1, m);
        s2 += __shfl_xor_sync(0xffffffffu, s2, m);
    }
    if (lane == 0) out[q] = 0.5f * (sqrtf(s1) + sqrtf(s2));
}

// ---------------- launch ----------------
extern "C" void kernel_launch(void* const* d_in, const int* in_sizes, int n_in,
                              void* d_out, int out_size) {
    const float* X  = (const float*)d_in[0];
    const float* cb = (const float*)d_in[1];
    int N  = in_sizes[0] / DD;
    int nq = N - SS;
    float* out = (float*)d_out;

    cudaFuncSetAttribute(k_gemm_argmax, cudaFuncAttributeMaxDynamicSharedMemorySize, SMEM_NEED);

    k_convert<<<512, 256>>>(cb);
    k_gemm_argmax<<<NPANELS, 256, SMEM_NEED>>>(X);
    k_hist<<<148, 256>>>();
    k_pcode<<<CC / PC_CHUNK, DD>>>(cb);
    k_finalize<<<1, DD>>>();
    k_query<<<(nq + 7) / 8, 256>>>(X, out, nq);
}